// round 1
// baseline (speedup 1.0000x reference)
#include <cuda_runtime.h>
#include <math.h>

// Problem dims (fixed)
#define NB 32
#define NT 1024
#define NC 512
#define NL 252
#define NP 256
#define NS 128
#define NBT (NB*NT)

// Scratch (device globals — no allocations allowed)
static __device__ float g_q[NBT*NC];        // q projection
static __device__ float g_query[NBT*NC];    // LN1 output
static __device__ float g_tmp[NBT*NC];      // attn_out, then ff
static __device__ float g_h[NBT*2*NC];      // FF hidden
static __device__ float g_attn[NBT*NS];     // scores -> attn probs
static __device__ float g_k[NB*NS*NC];
static __device__ float g_v[NB*NS*NC];

// ---------------------------------------------------------------------------
// K/V via rank-1 conditioner structure:
//   cond[b,s,j] = conv_w[s]*pad[b,j] + conv_b[s]
//   k[b,s,c]    = conv_w[s]*(pad[b]·Wk[c]) + conv_b[s]*sum(Wk[c]) + bk[c]
// ---------------------------------------------------------------------------
__global__ void cond_kv_kernel(const float* __restrict__ cond_emb,
                               const float* __restrict__ Wk, const float* __restrict__ bk,
                               const float* __restrict__ Wv, const float* __restrict__ bv,
                               const float* __restrict__ conv_w, const float* __restrict__ conv_b)
{
    int b = blockIdx.y;
    int c = blockIdx.x * blockDim.x + threadIdx.x;   // 0..511
    __shared__ float pad[NP];
    const float* ce = cond_emb + (long long)b * NL;
    for (int j = threadIdx.x; j < NP; j += blockDim.x)
        pad[j] = ce[(j + NL - 2) % NL];              // circular pad by 2
    __syncthreads();

    float pk = 0.f, pv = 0.f, wks = 0.f, wvs = 0.f;
    const float* wkr = Wk + (long long)c * NP;
    const float* wvr = Wv + (long long)c * NP;
#pragma unroll 4
    for (int j = 0; j < NP; j++) {
        float p = pad[j];
        float a = wkr[j], bbv = wvr[j];
        pk += p * a;  wks += a;
        pv += p * bbv; wvs += bbv;
    }
    float bkc = bk[c], bvc = bv[c];
    for (int s = 0; s < NS; s++) {
        float cw = conv_w[s], cb = conv_b[s];
        g_k[((long long)b*NS + s)*NC + c] = cw*pk + cb*wks + bkc;
        g_v[((long long)b*NS + s)*NC + c] = cw*pv + cb*wvs + bvc;
    }
}

// ---------------------------------------------------------------------------
// Tiled SGEMM: C[m,n] = scale * sum_k A[m,k]*B(n,k or k,n) + bias[n], EPI
//   BT_=true : B row-major [N][K] (NT gemm — weights, k tiles)
//   BT_=false: B row-major [K][N] (NN gemm — attn @ v)
//   EPI: 0 = none, 1 = exact GELU
// BM=BN=128, BK=16, 256 threads, 8x8 per thread. All dims divide tiles.
// ---------------------------------------------------------------------------
template<bool BT_, int EPI>
__global__ void __launch_bounds__(256)
sgemm_kernel(const float* __restrict__ A, const float* __restrict__ B,
             const float* __restrict__ bias, float* __restrict__ C,
             int M, int N, int K, float scale,
             long long sA, long long sB, long long sC)
{
    __shared__ float As[16][132];
    __shared__ float Bs[16][132];
    const int tid = threadIdx.x;
    const int tx = tid & 15, ty = tid >> 4;
    const int n0 = blockIdx.x * 128;
    const int m0 = blockIdx.y * 128;
    A += (long long)blockIdx.z * sA;
    B += (long long)blockIdx.z * sB;
    C += (long long)blockIdx.z * sC;

    float acc[8][8];
#pragma unroll
    for (int i = 0; i < 8; i++)
#pragma unroll
        for (int j = 0; j < 8; j++) acc[i][j] = 0.f;

    for (int k0 = 0; k0 < K; k0 += 16) {
        // Stage A tile: 128 rows x 16 k, transposed to As[k][m]
#pragma unroll
        for (int it = 0; it < 2; it++) {
            int idx = tid + it*256;
            int row = idx >> 2, c4 = (idx & 3) * 4;
            float4 a4 = *(const float4*)(A + (long long)(m0+row)*K + k0 + c4);
            As[c4+0][row] = a4.x; As[c4+1][row] = a4.y;
            As[c4+2][row] = a4.z; As[c4+3][row] = a4.w;
        }
        if (BT_) {
#pragma unroll
            for (int it = 0; it < 2; it++) {
                int idx = tid + it*256;
                int row = idx >> 2, c4 = (idx & 3) * 4;
                float4 b4 = *(const float4*)(B + (long long)(n0+row)*K + k0 + c4);
                Bs[c4+0][row] = b4.x; Bs[c4+1][row] = b4.y;
                Bs[c4+2][row] = b4.z; Bs[c4+3][row] = b4.w;
            }
        } else {
#pragma unroll
            for (int it = 0; it < 2; it++) {
                int idx = tid + it*256;
                int row = idx >> 5, c4 = (idx & 31) * 4;
                float4 b4 = *(const float4*)(B + (long long)(k0+row)*N + n0 + c4);
                *(float4*)&Bs[row][c4] = b4;
            }
        }
        __syncthreads();
#pragma unroll
        for (int kk = 0; kk < 16; kk++) {
            float ra[8], rb[8];
            *(float4*)&ra[0] = *(const float4*)&As[kk][ty*8];
            *(float4*)&ra[4] = *(const float4*)&As[kk][ty*8+4];
            *(float4*)&rb[0] = *(const float4*)&Bs[kk][tx*8];
            *(float4*)&rb[4] = *(const float4*)&Bs[kk][tx*8+4];
#pragma unroll
            for (int i = 0; i < 8; i++)
#pragma unroll
                for (int j = 0; j < 8; j++)
                    acc[i][j] += ra[i] * rb[j];
        }
        __syncthreads();
    }

#pragma unroll
    for (int i = 0; i < 8; i++) {
        int m = m0 + ty*8 + i;
#pragma unroll
        for (int j4 = 0; j4 < 2; j4++) {
            int n = n0 + tx*8 + j4*4;
            float4 r;
            float* pr = &r.x;
#pragma unroll
            for (int j = 0; j < 4; j++) {
                float vv = acc[i][j4*4+j] * scale;
                if (bias) vv += bias[n+j];
                if (EPI == 1) vv = 0.5f * vv * (1.0f + erff(vv * 0.70710678118654752f));
                pr[j] = vv;
            }
            *(float4*)(C + (long long)m*N + n) = r;
        }
    }
}

// ---------------------------------------------------------------------------
// Softmax over S=128, one warp per row, in-place on g_attn
// ---------------------------------------------------------------------------
__global__ void softmax_kernel()
{
    long long row = (long long)blockIdx.x * 8 + threadIdx.y;
    float* p = g_attn + row * NS;
    int lane = threadIdx.x;
    float4 v = ((float4*)p)[lane];
    float mx = fmaxf(fmaxf(v.x, v.y), fmaxf(v.z, v.w));
#pragma unroll
    for (int o = 16; o; o >>= 1) mx = fmaxf(mx, __shfl_xor_sync(0xffffffffu, mx, o));
    v.x = expf(v.x - mx); v.y = expf(v.y - mx);
    v.z = expf(v.z - mx); v.w = expf(v.w - mx);
    float s = v.x + v.y + v.z + v.w;
#pragma unroll
    for (int o = 16; o; o >>= 1) s += __shfl_xor_sync(0xffffffffu, s, o);
    float inv = 1.0f / s;
    v.x *= inv; v.y *= inv; v.z *= inv; v.w *= inv;
    ((float4*)p)[lane] = v;
}

// ---------------------------------------------------------------------------
// out = LN(a + b)*w + bb  (+ addx if non-null). One block (128 thr) per row.
// ---------------------------------------------------------------------------
__global__ void ln_kernel(const float* __restrict__ a, const float* __restrict__ b,
                          const float* __restrict__ w, const float* __restrict__ bb,
                          const float* __restrict__ addx, float* __restrict__ out)
{
    long long row = blockIdx.x;
    int t = threadIdx.x;
    float4 av = ((const float4*)(a + row*NC))[t];
    float4 bv = ((const float4*)(b + row*NC))[t];
    float4 u; u.x = av.x+bv.x; u.y = av.y+bv.y; u.z = av.z+bv.z; u.w = av.w+bv.w;
    float s  = u.x + u.y + u.z + u.w;
    float sq = u.x*u.x + u.y*u.y + u.z*u.z + u.w*u.w;
#pragma unroll
    for (int o = 16; o; o >>= 1) {
        s  += __shfl_xor_sync(0xffffffffu, s,  o);
        sq += __shfl_xor_sync(0xffffffffu, sq, o);
    }
    __shared__ float ss[4], sqs[4];
    int wid = t >> 5, lane = t & 31;
    if (lane == 0) { ss[wid] = s; sqs[wid] = sq; }
    __syncthreads();
    s  = ss[0] + ss[1] + ss[2] + ss[3];
    sq = sqs[0] + sqs[1] + sqs[2] + sqs[3];
    float mu  = s * (1.0f / NC);
    float var = sq * (1.0f / NC) - mu * mu;
    float inv = rsqrtf(var + 1e-5f);
    float4 wv  = ((const float4*)w)[t];
    float4 bv2 = ((const float4*)bb)[t];
    float4 o;
    o.x = (u.x - mu) * inv * wv.x + bv2.x;
    o.y = (u.y - mu) * inv * wv.y + bv2.y;
    o.z = (u.z - mu) * inv * wv.z + bv2.z;
    o.w = (u.w - mu) * inv * wv.w + bv2.w;
    if (addx) {
        float4 xv = ((const float4*)(addx + row*NC))[t];
        o.x += xv.x; o.y += xv.y; o.z += xv.z; o.w += xv.w;
    }
    ((float4*)(out + row*NC))[t] = o;
}

// ---------------------------------------------------------------------------
extern "C" void kernel_launch(void* const* d_in, const int* in_sizes, int n_in,
                              void* d_out, int out_size)
{
    const float* x     = (const float*)d_in[0];
    const float* ce    = (const float*)d_in[1];
    const float* Wq    = (const float*)d_in[2];
    const float* bq    = (const float*)d_in[3];
    const float* Wk    = (const float*)d_in[4];
    const float* bk    = (const float*)d_in[5];
    const float* Wv    = (const float*)d_in[6];
    const float* bv    = (const float*)d_in[7];
    const float* convw = (const float*)d_in[8];
    const float* convb = (const float*)d_in[9];
    const float* ln1w  = (const float*)d_in[10];
    const float* ln1b  = (const float*)d_in[11];
    const float* W1    = (const float*)d_in[12];
    const float* b1    = (const float*)d_in[13];
    const float* W2    = (const float*)d_in[14];
    const float* b2    = (const float*)d_in[15];
    const float* ln2w  = (const float*)d_in[16];
    const float* ln2b  = (const float*)d_in[17];
    float* out = (float*)d_out;

    float *q, *query, *tmp, *h, *attn, *kbuf, *vbuf;
    cudaGetSymbolAddress((void**)&q,     g_q);
    cudaGetSymbolAddress((void**)&query, g_query);
    cudaGetSymbolAddress((void**)&tmp,   g_tmp);
    cudaGetSymbolAddress((void**)&h,     g_h);
    cudaGetSymbolAddress((void**)&attn,  g_attn);
    cudaGetSymbolAddress((void**)&kbuf,  g_k);
    cudaGetSymbolAddress((void**)&vbuf,  g_v);

    const float scl = 0.04419417382415922f;  // 1/sqrt(512)

    // 1) K/V from rank-1 conditioner
    cond_kv_kernel<<<dim3(NC/128, NB), 128>>>(ce, Wk, bk, Wv, bv, convw, convb);

    // 2) q = x @ Wq^T + bq
    sgemm_kernel<true,0><<<dim3(NC/128, NBT/128, 1), 256>>>(
        x, Wq, bq, q, NBT, NC, NC, 1.0f, 0, 0, 0);

    // 3) scores = q @ k^T * scale  (batched over B)
    sgemm_kernel<true,0><<<dim3(NS/128, NT/128, NB), 256>>>(
        q, kbuf, nullptr, attn, NT, NS, NC, scl,
        (long long)NT*NC, (long long)NS*NC, (long long)NT*NS);

    // 4) softmax over S
    softmax_kernel<<<NBT/8, dim3(32,8)>>>();

    // 5) attn_out = attn @ v  (batched, NN)
    sgemm_kernel<false,0><<<dim3(NC/128, NT/128, NB), 256>>>(
        attn, vbuf, nullptr, tmp, NT, NC, NS, 1.0f,
        (long long)NT*NS, (long long)NS*NC, (long long)NT*NC);

    // 6) query = LN1(q + attn_out)
    ln_kernel<<<NBT, 128>>>(q, tmp, ln1w, ln1b, nullptr, query);

    // 7) h = gelu(query @ W1^T + b1)
    sgemm_kernel<true,1><<<dim3(2*NC/128, NBT/128, 1), 256>>>(
        query, W1, b1, h, NBT, 2*NC, NC, 1.0f, 0, 0, 0);

    // 8) ff = h @ W2^T + b2
    sgemm_kernel<true,0><<<dim3(NC/128, NBT/128, 1), 256>>>(
        h, W2, b2, tmp, NBT, NC, 2*NC, 1.0f, 0, 0, 0);

    // 9) out = LN2(query + ff) + x
    ln_kernel<<<NBT, 128>>>(query, tmp, ln2w, ln2b, x, out);
}

// round 3
// speedup vs baseline: 1.8766x; 1.8766x over previous
#include <cuda_runtime.h>
#include <math.h>
#include <cstdint>

// Problem dims (fixed)
#define NB 32
#define NT 1024
#define NC 512
#define NL 252
#define NP 256
#define NS 128
#define NBT (NB*NT)

// Scratch (device globals)
static __device__ float g_q[NBT*NC];
static __device__ float g_query[NBT*NC];
static __device__ float g_tmp[NBT*NC];
static __device__ float g_h[NBT*2*NC];
static __device__ float g_attn[NBT*NS];
static __device__ float g_k[NB*NS*NC];
static __device__ float g_vT[NB*NC*NS];
static __device__ float g_xr[NBT*NC];
static __device__ float g_wq[NC*NC];
static __device__ float g_w1[2*NC*NC];
static __device__ float g_w2[NC*2*NC];

// ---------------------------------------------------------------------------
__device__ __forceinline__ float rtf32(float x) {        // RNE round to tf32
    uint32_t u = __float_as_uint(x);
    u = (u + 0xfffu + ((u >> 13) & 1u)) & 0xffffe000u;
    return __uint_as_float(u);
}

__device__ __forceinline__ uint32_t smem_u32(const void* p) {
    uint32_t a;
    asm("{ .reg .u64 t; cvta.to.shared.u64 t, %1; cvt.u32.u64 %0, t; }" : "=r"(a) : "l"(p));
    return a;
}

__device__ __forceinline__ void cp16(uint32_t dst, const void* src) {
    asm volatile("cp.async.cg.shared.global [%0], [%1], 16;" :: "r"(dst), "l"(src) : "memory");
}
template<int N> __device__ __forceinline__ void cp_wait() {
    asm volatile("cp.async.wait_group %0;" :: "n"(N) : "memory");
}
__device__ __forceinline__ void cp_commit() { asm volatile("cp.async.commit_group;" ::: "memory"); }

// m16n8k8 tf32 MMA, fp32 accumulate
__device__ __forceinline__ void mma8(float* c, const float* a, const float* b) {
    asm volatile(
        "mma.sync.aligned.m16n8k8.row.col.f32.tf32.tf32.f32 "
        "{%0,%1,%2,%3}, {%4,%5,%6,%7}, {%8,%9}, {%0,%1,%2,%3};"
        : "+f"(c[0]), "+f"(c[1]), "+f"(c[2]), "+f"(c[3])
        : "r"(__float_as_uint(a[0])), "r"(__float_as_uint(a[1])),
          "r"(__float_as_uint(a[2])), "r"(__float_as_uint(a[3])),
          "r"(__float_as_uint(b[0])), "r"(__float_as_uint(b[1])));
}

// ---------------------------------------------------------------------------
// tf32 HMMA GEMM: C[m,n] = scale * A[m,:]·B[n,:] (+bias) (+GELU), rtf32 output
// A: [M,K] K-major, B: [N,K] K-major. CTA tile 128x128, BK=32, 256 threads.
// Warp grid 2(m) x 4(n) -> warp tile 64x32 via m16n8k8 (4x4 mma tiles).
// Smem: [row][k] with stride 36 floats (pad 4) -> conflict-free fragment LDS.
// Double-buffered cp.async staging.
// ---------------------------------------------------------------------------
#define STG_FLT (128*36)                 // floats per matrix per stage
#define GEMM_SMEM (2*2*STG_FLT*4)        // 73728 bytes

template<int EPI>
__global__ void __launch_bounds__(256)
gemm_tc(const float* __restrict__ A, const float* __restrict__ B,
        const float* __restrict__ bias, float* __restrict__ C,
        int K, int ldc, float scale,
        long long sA, long long sB, long long sC)
{
    extern __shared__ float sm[];
    const uint32_t sbase = smem_u32(sm);
    const int tid = threadIdx.x;
    const int wid = tid >> 5, lane = tid & 31;
    const int g = lane >> 2, tig = lane & 3;
    const int wm = wid & 1, wn = wid >> 1;
    const int m0 = blockIdx.y * 128, n0 = blockIdx.x * 128;
    A += blockIdx.z * sA + (long long)m0 * K;
    B += blockIdx.z * sB + (long long)n0 * K;
    C += blockIdx.z * sC;
    const int nk = K >> 5;

    float acc[4][4][4];
#pragma unroll
    for (int i = 0; i < 4; i++)
#pragma unroll
        for (int j = 0; j < 4; j++)
#pragma unroll
            for (int q = 0; q < 4; q++) acc[i][j][q] = 0.f;

    // stage one K-chunk: A 128x32 + B 128x32 into [row][k] stride-36 smem
    auto stage = [&](int chunk, int stg) {
        uint32_t ab = sbase + stg * (2 * STG_FLT * 4);
        uint32_t bb = ab + STG_FLT * 4;
        const float* Ac = A + chunk * 32;
        const float* Bc = B + chunk * 32;
#pragma unroll
        for (int i = 0; i < 4; i++) {
            int idx = i * 256 + tid;            // 0..1023
            int row = idx >> 3, c4 = (idx & 7) * 4;
            uint32_t so = (row * 36 + c4) * 4;
            cp16(ab + so, Ac + (long long)row * K + c4);
            cp16(bb + so, Bc + (long long)row * K + c4);
        }
        cp_commit();
    };

    stage(0, 0);

    for (int kc = 0; kc < nk; kc++) {
        if (kc + 1 < nk) { stage(kc + 1, (kc + 1) & 1); cp_wait<1>(); }
        else            { cp_wait<0>(); }
        __syncthreads();

        const float* As = sm + (kc & 1) * (2 * STG_FLT);
        const float* Bs = As + STG_FLT;
        const float* Aw = As + (wm * 64) * 36;
        const float* Bw = Bs + (wn * 32) * 36;
#pragma unroll
        for (int ks = 0; ks < 4; ks++) {
            int k = ks * 8;
            float af[4][4], bf[4][2];
#pragma unroll
            for (int mt = 0; mt < 4; mt++) {
                const float* p = Aw + (mt * 16 + g) * 36 + k;
                af[mt][0] = p[tig];
                af[mt][1] = p[8 * 36 + tig];
                af[mt][2] = p[tig + 4];
                af[mt][3] = p[8 * 36 + tig + 4];
            }
#pragma unroll
            for (int nt = 0; nt < 4; nt++) {
                const float* p = Bw + (nt * 8 + g) * 36 + k;
                bf[nt][0] = p[tig];
                bf[nt][1] = p[tig + 4];
            }
#pragma unroll
            for (int mt = 0; mt < 4; mt++)
#pragma unroll
                for (int nt = 0; nt < 4; nt++)
                    mma8(acc[mt][nt], af[mt], bf[nt]);
        }
        __syncthreads();
    }

    // Epilogue
#pragma unroll
    for (int mt = 0; mt < 4; mt++) {
#pragma unroll
        for (int half = 0; half < 2; half++) {
            int row = m0 + wm * 64 + mt * 16 + g + half * 8;
            float* Crow = C + (long long)row * ldc;
#pragma unroll
            for (int nt = 0; nt < 4; nt++) {
                int col = n0 + wn * 32 + nt * 8 + 2 * tig;
                float v0 = acc[mt][nt][half * 2 + 0] * scale;
                float v1 = acc[mt][nt][half * 2 + 1] * scale;
                if (bias) { v0 += bias[col]; v1 += bias[col + 1]; }
                if (EPI == 1) {
                    v0 = 0.5f * v0 * (1.0f + erff(v0 * 0.70710678118654752f));
                    v1 = 0.5f * v1 * (1.0f + erff(v1 * 0.70710678118654752f));
                }
                float2 o; o.x = rtf32(v0); o.y = rtf32(v1);
                *(float2*)(Crow + col) = o;
            }
        }
    }
}

// ---------------------------------------------------------------------------
// K/V via rank-1 conditioner; writes k[b][s][c] and vT[b][c][s], tf32-rounded
// ---------------------------------------------------------------------------
__global__ void cond_kv_kernel(const float* __restrict__ cond_emb,
                               const float* __restrict__ Wk, const float* __restrict__ bk,
                               const float* __restrict__ Wv, const float* __restrict__ bv,
                               const float* __restrict__ conv_w, const float* __restrict__ conv_b)
{
    int b = blockIdx.y;
    int c = blockIdx.x * blockDim.x + threadIdx.x;
    __shared__ float pad[NP];
    const float* ce = cond_emb + (long long)b * NL;
    for (int j = threadIdx.x; j < NP; j += blockDim.x)
        pad[j] = ce[(j + NL - 2) % NL];
    __syncthreads();

    float pk = 0.f, pv = 0.f, wks = 0.f, wvs = 0.f;
    const float* wkr = Wk + (long long)c * NP;
    const float* wvr = Wv + (long long)c * NP;
#pragma unroll 4
    for (int j = 0; j < NP; j++) {
        float p = pad[j];
        float a = wkr[j], bb = wvr[j];
        pk += p * a;  wks += a;
        pv += p * bb; wvs += bb;
    }
    float bkc = bk[c], bvc = bv[c];
    for (int s = 0; s < NS; s++) {
        float cw = conv_w[s], cb = conv_b[s];
        g_k[((long long)b * NS + s) * NC + c]  = rtf32(cw * pk + cb * wks + bkc);
        g_vT[((long long)b * NC + c) * NS + s] = rtf32(cw * pv + cb * wvs + bvc);
    }
}

// ---------------------------------------------------------------------------
__global__ void round_kernel(const float* __restrict__ s, float* __restrict__ d, int n4)
{
    int i = blockIdx.x * blockDim.x + threadIdx.x;
    if (i >= n4) return;
    float4 v = ((const float4*)s)[i];
    v.x = rtf32(v.x); v.y = rtf32(v.y); v.z = rtf32(v.z); v.w = rtf32(v.w);
    ((float4*)d)[i] = v;
}

// ---------------------------------------------------------------------------
__global__ void softmax_kernel()
{
    long long row = (long long)blockIdx.x * 8 + threadIdx.y;
    float* p = g_attn + row * NS;
    int lane = threadIdx.x;
    float4 v = ((float4*)p)[lane];
    float mx = fmaxf(fmaxf(v.x, v.y), fmaxf(v.z, v.w));
#pragma unroll
    for (int o = 16; o; o >>= 1) mx = fmaxf(mx, __shfl_xor_sync(0xffffffffu, mx, o));
    v.x = expf(v.x - mx); v.y = expf(v.y - mx);
    v.z = expf(v.z - mx); v.w = expf(v.w - mx);
    float s = v.x + v.y + v.z + v.w;
#pragma unroll
    for (int o = 16; o; o >>= 1) s += __shfl_xor_sync(0xffffffffu, s, o);
    float inv = 1.0f / s;
    v.x = rtf32(v.x * inv); v.y = rtf32(v.y * inv);
    v.z = rtf32(v.z * inv); v.w = rtf32(v.w * inv);
    ((float4*)p)[lane] = v;
}

// ---------------------------------------------------------------------------
template<int R>
__global__ void ln_kernel(const float* __restrict__ a, const float* __restrict__ b,
                          const float* __restrict__ w, const float* __restrict__ bb,
                          const float* __restrict__ addx, float* __restrict__ out)
{
    long long row = blockIdx.x;
    int t = threadIdx.x;
    float4 av = ((const float4*)(a + row * NC))[t];
    float4 bv = ((const float4*)(b + row * NC))[t];
    float4 u; u.x = av.x + bv.x; u.y = av.y + bv.y; u.z = av.z + bv.z; u.w = av.w + bv.w;
    float s  = u.x + u.y + u.z + u.w;
    float sq = u.x*u.x + u.y*u.y + u.z*u.z + u.w*u.w;
#pragma unroll
    for (int o = 16; o; o >>= 1) {
        s  += __shfl_xor_sync(0xffffffffu, s,  o);
        sq += __shfl_xor_sync(0xffffffffu, sq, o);
    }
    __shared__ float ss[4], sqs[4];
    int wid = t >> 5, lane = t & 31;
    if (lane == 0) { ss[wid] = s; sqs[wid] = sq; }
    __syncthreads();
    s  = ss[0] + ss[1] + ss[2] + ss[3];
    sq = sqs[0] + sqs[1] + sqs[2] + sqs[3];
    float mu  = s * (1.0f / NC);
    float var = sq * (1.0f / NC) - mu * mu;
    float inv = rsqrtf(var + 1e-5f);
    float4 wv  = ((const float4*)w)[t];
    float4 bv2 = ((const float4*)bb)[t];
    float4 o;
    o.x = (u.x - mu) * inv * wv.x + bv2.x;
    o.y = (u.y - mu) * inv * wv.y + bv2.y;
    o.z = (u.z - mu) * inv * wv.z + bv2.z;
    o.w = (u.w - mu) * inv * wv.w + bv2.w;
    if (addx) {
        float4 xv = ((const float4*)(addx + row * NC))[t];
        o.x += xv.x; o.y += xv.y; o.z += xv.z; o.w += xv.w;
    }
    if (R) { o.x = rtf32(o.x); o.y = rtf32(o.y); o.z = rtf32(o.z); o.w = rtf32(o.w); }
    ((float4*)(out + row * NC))[t] = o;
}

// ---------------------------------------------------------------------------
extern "C" void kernel_launch(void* const* d_in, const int* in_sizes, int n_in,
                              void* d_out, int out_size)
{
    const float* x     = (const float*)d_in[0];
    const float* ce    = (const float*)d_in[1];
    const float* Wq    = (const float*)d_in[2];
    const float* bq    = (const float*)d_in[3];
    const float* Wk    = (const float*)d_in[4];
    const float* bk    = (const float*)d_in[5];
    const float* Wv    = (const float*)d_in[6];
    const float* bv    = (const float*)d_in[7];
    const float* convw = (const float*)d_in[8];
    const float* convb = (const float*)d_in[9];
    const float* ln1w  = (const float*)d_in[10];
    const float* ln1b  = (const float*)d_in[11];
    const float* W1    = (const float*)d_in[12];
    const float* b1    = (const float*)d_in[13];
    const float* W2    = (const float*)d_in[14];
    const float* b2    = (const float*)d_in[15];
    const float* ln2w  = (const float*)d_in[16];
    const float* ln2b  = (const float*)d_in[17];
    float* out = (float*)d_out;

    float *q, *query, *tmp, *h, *attn, *kbuf, *vT, *xr, *wq, *w1, *w2;
    cudaGetSymbolAddress((void**)&q,     g_q);
    cudaGetSymbolAddress((void**)&query, g_query);
    cudaGetSymbolAddress((void**)&tmp,   g_tmp);
    cudaGetSymbolAddress((void**)&h,     g_h);
    cudaGetSymbolAddress((void**)&attn,  g_attn);
    cudaGetSymbolAddress((void**)&kbuf,  g_k);
    cudaGetSymbolAddress((void**)&vT,    g_vT);
    cudaGetSymbolAddress((void**)&xr,    g_xr);
    cudaGetSymbolAddress((void**)&wq,    g_wq);
    cudaGetSymbolAddress((void**)&w1,    g_w1);
    cudaGetSymbolAddress((void**)&w2,    g_w2);

    cudaFuncSetAttribute(gemm_tc<0>, cudaFuncAttributeMaxDynamicSharedMemorySize, GEMM_SMEM);
    cudaFuncSetAttribute(gemm_tc<1>, cudaFuncAttributeMaxDynamicSharedMemorySize, GEMM_SMEM);

    const float scl = 0.04419417382415922f;  // 1/sqrt(512)

    // Pre-round operands to tf32
    round_kernel<<<(NBT*NC/4 + 255)/256, 256>>>(x,  xr, NBT*NC/4);
    round_kernel<<<(NC*NC/4   + 255)/256, 256>>>(Wq, wq, NC*NC/4);
    round_kernel<<<(2*NC*NC/4 + 255)/256, 256>>>(W1, w1, 2*NC*NC/4);
    round_kernel<<<(2*NC*NC/4 + 255)/256, 256>>>(W2, w2, 2*NC*NC/4);

    // 1) K/V from rank-1 conditioner
    cond_kv_kernel<<<dim3(NC/128, NB), 128>>>(ce, Wk, bk, Wv, bv, convw, convb);

    // 2) q = x @ Wq^T + bq
    gemm_tc<0><<<dim3(NC/128, NBT/128, 1), 256, GEMM_SMEM>>>(
        xr, wq, bq, q, NC, NC, 1.0f, 0, 0, 0);

    // 3) scores = q @ k^T * scale (batched over B)
    gemm_tc<0><<<dim3(1, NT/128, NB), 256, GEMM_SMEM>>>(
        q, kbuf, nullptr, attn, NC, NS, scl,
        (long long)NT*NC, (long long)NS*NC, (long long)NT*NS);

    // 4) softmax over S
    softmax_kernel<<<NBT/8, dim3(32, 8)>>>();

    // 5) attn_out = attn @ vT^T (batched)
    gemm_tc<0><<<dim3(NC/128, NT/128, NB), 256, GEMM_SMEM>>>(
        attn, vT, nullptr, tmp, NS, NC, 1.0f,
        (long long)NT*NS, (long long)NC*NS, (long long)NT*NC);

    // 6) query = LN1(q + attn_out)
    ln_kernel<1><<<NBT, 128>>>(q, tmp, ln1w, ln1b, nullptr, query);

    // 7) h = gelu(query @ W1^T + b1)
    gemm_tc<1><<<dim3(2*NC/128, NBT/128, 1), 256, GEMM_SMEM>>>(
        query, w1, b1, h, NC, 2*NC, 1.0f, 0, 0, 0);

    // 8) ff = h @ W2^T + b2
    gemm_tc<0><<<dim3(NC/128, NBT/128, 1), 256, GEMM_SMEM>>>(
        h, w2, b2, tmp, 2*NC, NC, 1.0f, 0, 0, 0);

    // 9) out = LN2(query + ff) + x
    ln_kernel<0><<<NBT, 128>>>(query, tmp, ln2w, ln2b, x, out);
}

// round 4
// speedup vs baseline: 3.7659x; 2.0068x over previous
#include <cuda_runtime.h>
#include <cuda_fp16.h>
#include <math.h>
#include <cstdint>

// Problem dims (fixed)
#define NB 32
#define NT 1024
#define NC 512
#define NL 252
#define NP 256
#define NS 128
#define NBT (NB*NT)

// fp32 scratch
static __device__ float g_q[NBT*NC];
static __device__ float g_query[NBT*NC];
static __device__ float g_tmp[NBT*NC];
static __device__ float g_attn[NBT*NS];
// fp16 scratch
static __device__ __half g_xh[NBT*NC];
static __device__ __half g_qh[NBT*NC];
static __device__ __half g_queryh[NBT*NC];
static __device__ __half g_hh[NBT*2*NC];
static __device__ __half g_attnh[NBT*NS];
static __device__ __half g_kh[NB*NS*NC];
static __device__ __half g_vTh[NB*NC*NS];
static __device__ __half g_wqh[NC*NC];
static __device__ __half g_w1h[2*NC*NC];
static __device__ __half g_w2h[NC*2*NC];

// ---------------------------------------------------------------------------
__device__ __forceinline__ uint32_t smem_u32(const void* p) {
    uint32_t a;
    asm("{ .reg .u64 t; cvta.to.shared.u64 t, %1; cvt.u32.u64 %0, t; }" : "=r"(a) : "l"(p));
    return a;
}
__device__ __forceinline__ void cp16(uint32_t dst, const void* src) {
    asm volatile("cp.async.cg.shared.global [%0], [%1], 16;" :: "r"(dst), "l"(src) : "memory");
}
template<int N> __device__ __forceinline__ void cp_wait() {
    asm volatile("cp.async.wait_group %0;" :: "n"(N) : "memory");
}
__device__ __forceinline__ void cp_commit() { asm volatile("cp.async.commit_group;" ::: "memory"); }

// m16n8k16 fp16 MMA, fp32 accumulate
__device__ __forceinline__ void mma16(float* c, const uint32_t* a, const uint32_t* b) {
    asm volatile(
        "mma.sync.aligned.m16n8k16.row.col.f32.f16.f16.f32 "
        "{%0,%1,%2,%3}, {%4,%5,%6,%7}, {%8,%9}, {%0,%1,%2,%3};"
        : "+f"(c[0]), "+f"(c[1]), "+f"(c[2]), "+f"(c[3])
        : "r"(a[0]), "r"(a[1]), "r"(a[2]), "r"(a[3]), "r"(b[0]), "r"(b[1]));
}

// ---------------------------------------------------------------------------
// fp16 HMMA GEMM: C[m,n] = scale * A[m,:]·B[n,:] (+bias) (+GELU)
// A: [M,K] K-major half, B: [N,K] K-major half. CTA 128x128, BK=32, 256 thr.
// Warp grid 2(m) x 4(n) -> warp tile 64x32, m16n8k16, 2 k16 slabs per chunk.
// Smem rows stride 40 halves (20 words) -> conflict-free fragment LDS.
// Outputs: optional fp32 C and/or fp16 Ch.
// ---------------------------------------------------------------------------
#define SROWW 20                       // words per smem row
#define STG_WORDS (128*SROWW)          // words per matrix per stage (2560)
#define GEMM_SMEM (2*2*STG_WORDS*4)    // 40960 bytes

template<int EPI>
__global__ void __launch_bounds__(256)
gemm_h(const __half* __restrict__ A, const __half* __restrict__ B,
       const float* __restrict__ bias, float* __restrict__ C, __half* __restrict__ Ch,
       int K, int ldc, float scale,
       long long sA, long long sB, long long sC)
{
    extern __shared__ uint32_t smw[];
    const uint32_t sbase = smem_u32(smw);
    const int tid = threadIdx.x;
    const int wid = tid >> 5, lane = tid & 31;
    const int g = lane >> 2, tig = lane & 3;
    const int wm = wid & 1, wn = wid >> 1;
    const int m0 = blockIdx.y * 128, n0 = blockIdx.x * 128;
    A += blockIdx.z * sA + (long long)m0 * K;
    B += blockIdx.z * sB + (long long)n0 * K;
    if (C)  C  += blockIdx.z * sC;
    if (Ch) Ch += blockIdx.z * sC;
    const int nk = K >> 5;

    float acc[4][4][4];
#pragma unroll
    for (int i = 0; i < 4; i++)
#pragma unroll
        for (int j = 0; j < 4; j++)
#pragma unroll
            for (int q = 0; q < 4; q++) acc[i][j][q] = 0.f;

    // stage one K-chunk: A 128x32 + B 128x32 halves, rows padded to 80B
    auto stage = [&](int chunk, int stg) {
        uint32_t ab = sbase + stg * (2 * STG_WORDS * 4);
        uint32_t bb = ab + STG_WORDS * 4;
        const __half* Ac = A + chunk * 32;
        const __half* Bc = B + chunk * 32;
#pragma unroll
        for (int i = 0; i < 2; i++) {
            int idx = i * 256 + tid;           // 0..511
            int row = idx >> 2, c8 = idx & 3;  // 16B = 8 halves
            uint32_t so = row * 80 + c8 * 16;
            cp16(ab + so, Ac + (long long)row * K + c8 * 8);
            cp16(bb + so, Bc + (long long)row * K + c8 * 8);
        }
        cp_commit();
    };

    stage(0, 0);

    for (int kc = 0; kc < nk; kc++) {
        if (kc + 1 < nk) { stage(kc + 1, (kc + 1) & 1); cp_wait<1>(); }
        else            { cp_wait<0>(); }
        __syncthreads();

        const uint32_t* As = smw + (kc & 1) * (2 * STG_WORDS);
        const uint32_t* Bs = As + STG_WORDS;
        const uint32_t* Aw = As + (wm * 64) * SROWW;
        const uint32_t* Bw = Bs + (wn * 32) * SROWW;
#pragma unroll
        for (int slab = 0; slab < 2; slab++) {
            int kw = slab * 8;
            uint32_t af[4][4], bf[4][2];
#pragma unroll
            for (int mt = 0; mt < 4; mt++) {
                const uint32_t* p = Aw + (mt * 16 + g) * SROWW + kw;
                af[mt][0] = p[tig];
                af[mt][1] = p[8 * SROWW + tig];
                af[mt][2] = p[tig + 4];
                af[mt][3] = p[8 * SROWW + tig + 4];
            }
#pragma unroll
            for (int nt = 0; nt < 4; nt++) {
                const uint32_t* p = Bw + (nt * 8 + g) * SROWW + kw;
                bf[nt][0] = p[tig];
                bf[nt][1] = p[tig + 4];
            }
#pragma unroll
            for (int mt = 0; mt < 4; mt++)
#pragma unroll
                for (int nt = 0; nt < 4; nt++)
                    mma16(acc[mt][nt], af[mt], bf[nt]);
        }
        __syncthreads();
    }

    // Epilogue
#pragma unroll
    for (int mt = 0; mt < 4; mt++) {
#pragma unroll
        for (int half_ = 0; half_ < 2; half_++) {
            int row = m0 + wm * 64 + mt * 16 + g + half_ * 8;
#pragma unroll
            for (int nt = 0; nt < 4; nt++) {
                int col = n0 + wn * 32 + nt * 8 + 2 * tig;
                float v0 = acc[mt][nt][half_ * 2 + 0] * scale;
                float v1 = acc[mt][nt][half_ * 2 + 1] * scale;
                if (bias) { v0 += bias[col]; v1 += bias[col + 1]; }
                if (EPI == 1) {
                    v0 = 0.5f * v0 * (1.0f + erff(v0 * 0.70710678118654752f));
                    v1 = 0.5f * v1 * (1.0f + erff(v1 * 0.70710678118654752f));
                }
                if (C) {
                    float2 o; o.x = v0; o.y = v1;
                    *(float2*)(C + (long long)row * ldc + col) = o;
                }
                if (Ch)
                    *(__half2*)(Ch + (long long)row * ldc + col) = __floats2half2_rn(v0, v1);
            }
        }
    }
}

// ---------------------------------------------------------------------------
// K/V via rank-1 conditioner; writes kh[b][s][c] and vTh[b][c][s] (fp16)
// ---------------------------------------------------------------------------
__global__ void cond_kv_kernel(const float* __restrict__ cond_emb,
                               const float* __restrict__ Wk, const float* __restrict__ bk,
                               const float* __restrict__ Wv, const float* __restrict__ bv,
                               const float* __restrict__ conv_w, const float* __restrict__ conv_b)
{
    int b = blockIdx.y;
    int c = blockIdx.x * blockDim.x + threadIdx.x;
    __shared__ float pad[NP];
    const float* ce = cond_emb + (long long)b * NL;
    for (int j = threadIdx.x; j < NP; j += blockDim.x)
        pad[j] = ce[(j + NL - 2) % NL];
    __syncthreads();

    float pk = 0.f, pv = 0.f, wks = 0.f, wvs = 0.f;
    const float* wkr = Wk + (long long)c * NP;
    const float* wvr = Wv + (long long)c * NP;
#pragma unroll 4
    for (int j = 0; j < NP; j++) {
        float p = pad[j];
        float a = wkr[j], bb = wvr[j];
        pk += p * a;  wks += a;
        pv += p * bb; wvs += bb;
    }
    float bkc = bk[c], bvc = bv[c];
    for (int s = 0; s < NS; s++) {
        float cw = conv_w[s], cb = conv_b[s];
        g_kh[((long long)b * NS + s) * NC + c]  = __float2half_rn(cw * pk + cb * wks + bkc);
        g_vTh[((long long)b * NC + c) * NS + s] = __float2half_rn(cw * pv + cb * wvs + bvc);
    }
}

// ---------------------------------------------------------------------------
__global__ void cvt_half_kernel(const float* __restrict__ s, __half* __restrict__ d, int n4)
{
    int i = blockIdx.x * blockDim.x + threadIdx.x;
    if (i >= n4) return;
    float4 v = ((const float4*)s)[i];
    __half2 h0 = __floats2half2_rn(v.x, v.y);
    __half2 h1 = __floats2half2_rn(v.z, v.w);
    ((__half2*)d)[2*i]   = h0;
    ((__half2*)d)[2*i+1] = h1;
}

// ---------------------------------------------------------------------------
// Softmax over S=128: read fp32 scores, write fp16 probs
// ---------------------------------------------------------------------------
__global__ void softmax_kernel()
{
    long long row = (long long)blockIdx.x * 8 + threadIdx.y;
    const float* p = g_attn + row * NS;
    __half* ph = g_attnh + row * NS;
    int lane = threadIdx.x;
    float4 v = ((const float4*)p)[lane];
    float mx = fmaxf(fmaxf(v.x, v.y), fmaxf(v.z, v.w));
#pragma unroll
    for (int o = 16; o; o >>= 1) mx = fmaxf(mx, __shfl_xor_sync(0xffffffffu, mx, o));
    v.x = expf(v.x - mx); v.y = expf(v.y - mx);
    v.z = expf(v.z - mx); v.w = expf(v.w - mx);
    float s = v.x + v.y + v.z + v.w;
#pragma unroll
    for (int o = 16; o; o >>= 1) s += __shfl_xor_sync(0xffffffffu, s, o);
    float inv = 1.0f / s;
    __half2 h0 = __floats2half2_rn(v.x * inv, v.y * inv);
    __half2 h1 = __floats2half2_rn(v.z * inv, v.w * inv);
    *(__half2*)(ph + lane * 4)     = h0;
    *(__half2*)(ph + lane * 4 + 2) = h1;
}

// ---------------------------------------------------------------------------
// out = LN(a + b)*w + bb (+ addx). Optional fp16 copy out2.
// ---------------------------------------------------------------------------
__global__ void ln_kernel(const float* __restrict__ a, const float* __restrict__ b,
                          const float* __restrict__ w, const float* __restrict__ bb,
                          const float* __restrict__ addx, float* __restrict__ out,
                          __half* __restrict__ out2)
{
    long long row = blockIdx.x;
    int t = threadIdx.x;
    float4 av = ((const float4*)(a + row * NC))[t];
    float4 bv = ((const float4*)(b + row * NC))[t];
    float4 u; u.x = av.x + bv.x; u.y = av.y + bv.y; u.z = av.z + bv.z; u.w = av.w + bv.w;
    float s  = u.x + u.y + u.z + u.w;
    float sq = u.x*u.x + u.y*u.y + u.z*u.z + u.w*u.w;
#pragma unroll
    for (int o = 16; o; o >>= 1) {
        s  += __shfl_xor_sync(0xffffffffu, s,  o);
        sq += __shfl_xor_sync(0xffffffffu, sq, o);
    }
    __shared__ float ss[4], sqs[4];
    int wid = t >> 5, lane = t & 31;
    if (lane == 0) { ss[wid] = s; sqs[wid] = sq; }
    __syncthreads();
    s  = ss[0] + ss[1] + ss[2] + ss[3];
    sq = sqs[0] + sqs[1] + sqs[2] + sqs[3];
    float mu  = s * (1.0f / NC);
    float var = sq * (1.0f / NC) - mu * mu;
    float inv = rsqrtf(var + 1e-5f);
    float4 wv  = ((const float4*)w)[t];
    float4 bv2 = ((const float4*)bb)[t];
    float4 o;
    o.x = (u.x - mu) * inv * wv.x + bv2.x;
    o.y = (u.y - mu) * inv * wv.y + bv2.y;
    o.z = (u.z - mu) * inv * wv.z + bv2.z;
    o.w = (u.w - mu) * inv * wv.w + bv2.w;
    if (addx) {
        float4 xv = ((const float4*)(addx + row * NC))[t];
        o.x += xv.x; o.y += xv.y; o.z += xv.z; o.w += xv.w;
    }
    ((float4*)(out + row * NC))[t] = o;
    if (out2) {
        __half2 h0 = __floats2half2_rn(o.x, o.y);
        __half2 h1 = __floats2half2_rn(o.z, o.w);
        *(__half2*)(out2 + row * NC + t * 4)     = h0;
        *(__half2*)(out2 + row * NC + t * 4 + 2) = h1;
    }
}

// ---------------------------------------------------------------------------
extern "C" void kernel_launch(void* const* d_in, const int* in_sizes, int n_in,
                              void* d_out, int out_size)
{
    const float* x     = (const float*)d_in[0];
    const float* ce    = (const float*)d_in[1];
    const float* Wq    = (const float*)d_in[2];
    const float* bq    = (const float*)d_in[3];
    const float* Wk    = (const float*)d_in[4];
    const float* bk    = (const float*)d_in[5];
    const float* Wv    = (const float*)d_in[6];
    const float* bv    = (const float*)d_in[7];
    const float* convw = (const float*)d_in[8];
    const float* convb = (const float*)d_in[9];
    const float* ln1w  = (const float*)d_in[10];
    const float* ln1b  = (const float*)d_in[11];
    const float* W1    = (const float*)d_in[12];
    const float* b1    = (const float*)d_in[13];
    const float* W2    = (const float*)d_in[14];
    const float* b2    = (const float*)d_in[15];
    const float* ln2w  = (const float*)d_in[16];
    const float* ln2b  = (const float*)d_in[17];
    float* out = (float*)d_out;

    float *q, *query, *tmp, *attn;
    __half *xh, *qh, *queryh, *hh, *attnh, *kh, *vTh, *wqh, *w1h, *w2h;
    cudaGetSymbolAddress((void**)&q,      g_q);
    cudaGetSymbolAddress((void**)&query,  g_query);
    cudaGetSymbolAddress((void**)&tmp,    g_tmp);
    cudaGetSymbolAddress((void**)&attn,   g_attn);
    cudaGetSymbolAddress((void**)&xh,     g_xh);
    cudaGetSymbolAddress((void**)&qh,     g_qh);
    cudaGetSymbolAddress((void**)&queryh, g_queryh);
    cudaGetSymbolAddress((void**)&hh,     g_hh);
    cudaGetSymbolAddress((void**)&attnh,  g_attnh);
    cudaGetSymbolAddress((void**)&kh,     g_kh);
    cudaGetSymbolAddress((void**)&vTh,    g_vTh);
    cudaGetSymbolAddress((void**)&wqh,    g_wqh);
    cudaGetSymbolAddress((void**)&w1h,    g_w1h);
    cudaGetSymbolAddress((void**)&w2h,    g_w2h);

    cudaFuncSetAttribute(gemm_h<0>, cudaFuncAttributeMaxDynamicSharedMemorySize, GEMM_SMEM);
    cudaFuncSetAttribute(gemm_h<1>, cudaFuncAttributeMaxDynamicSharedMemorySize, GEMM_SMEM);

    const float scl = 0.04419417382415922f;  // 1/sqrt(512)

    // Convert operands to fp16
    cvt_half_kernel<<<(NBT*NC/4 + 255)/256, 256>>>(x,  xh,  NBT*NC/4);
    cvt_half_kernel<<<(NC*NC/4   + 255)/256, 256>>>(Wq, wqh, NC*NC/4);
    cvt_half_kernel<<<(2*NC*NC/4 + 255)/256, 256>>>(W1, w1h, 2*NC*NC/4);
    cvt_half_kernel<<<(2*NC*NC/4 + 255)/256, 256>>>(W2, w2h, 2*NC*NC/4);

    // 1) K/V from rank-1 conditioner
    cond_kv_kernel<<<dim3(NC/128, NB), 128>>>(ce, Wk, bk, Wv, bv, convw, convb);

    // 2) q = x @ Wq^T + bq  (fp32 + fp16 out)
    gemm_h<0><<<dim3(NC/128, NBT/128, 1), 256, GEMM_SMEM>>>(
        xh, wqh, bq, q, qh, NC, NC, 1.0f, 0, 0, 0);

    // 3) scores = q @ k^T * scale (batched over B), fp32 out
    gemm_h<0><<<dim3(1, NT/128, NB), 256, GEMM_SMEM>>>(
        qh, kh, nullptr, attn, nullptr, NC, NS, scl,
        (long long)NT*NC, (long long)NS*NC, (long long)NT*NS);

    // 4) softmax -> fp16 probs
    softmax_kernel<<<NBT/8, dim3(32, 8)>>>();

    // 5) attn_out = attn @ vT^T (batched), fp32 out
    gemm_h<0><<<dim3(NC/128, NT/128, NB), 256, GEMM_SMEM>>>(
        attnh, vTh, nullptr, tmp, nullptr, NS, NC, 1.0f,
        (long long)NT*NS, (long long)NC*NS, (long long)NT*NC);

    // 6) query = LN1(q + attn_out), fp32 + fp16
    ln_kernel<<<NBT, 128>>>(q, tmp, ln1w, ln1b, nullptr, query, queryh);

    // 7) h = gelu(query @ W1^T + b1), fp16 only
    gemm_h<1><<<dim3(2*NC/128, NBT/128, 1), 256, GEMM_SMEM>>>(
        queryh, w1h, b1, nullptr, hh, NC, 2*NC, 1.0f, 0, 0, 0);

    // 8) ff = h @ W2^T + b2, fp32 out
    gemm_h<0><<<dim3(NC/128, NBT/128, 1), 256, GEMM_SMEM>>>(
        hh, w2h, b2, tmp, nullptr, 2*NC, NC, 1.0f, 0, 0, 0);

    // 9) out = LN2(query + ff) + x
    ln_kernel<<<NBT, 128>>>(query, tmp, ln2w, ln2b, x, out, nullptr);
}